// round 6
// baseline (speedup 1.0000x reference)
#include <cuda_runtime.h>
#include <cstdint>

// Scratch for q, k, v: (4, 64, 64, 64) f32 each = 4 MB each. Static device
// arrays (allocation-free, per harness rules).
#define TOTAL_ELEMS (4 * 64 * 64 * 64)
__device__ float g_q[TOTAL_ELEMS];
__device__ float g_k[TOTAL_ELEMS];
__device__ float g_v[TOTAL_ELEMS];

__device__ __forceinline__ float ex2f(float x) {
    float y;
    asm("ex2.approx.ftz.f32 %0, %1;" : "=f"(y) : "f"(x));
    return y;
}

// Compile-time selector: element I (0..11) of three float4s. After full
// unrolling I is a constant, so this folds to a single register reference.
template <int I>
__device__ __forceinline__ float elt(const float4& a, const float4& b,
                                     const float4& c) {
    if constexpr (I == 0)  return a.x;
    else if constexpr (I == 1)  return a.y;
    else if constexpr (I == 2)  return a.z;
    else if constexpr (I == 3)  return a.w;
    else if constexpr (I == 4)  return b.x;
    else if constexpr (I == 5)  return b.y;
    else if constexpr (I == 6)  return b.z;
    else if constexpr (I == 7)  return b.w;
    else if constexpr (I == 8)  return c.x;
    else if constexpr (I == 9)  return c.y;
    else if constexpr (I == 10) return c.z;
    else                        return c.w;
}

// ---------------------------------------------------------------------------
// Kernel 1: fused grouped 1x1 convs -> q, k, v. (unchanged this round)
// Grid: (32, 4, 4): blockIdx.x = {pixel chunk [0,16)} x {oc half}.
// ---------------------------------------------------------------------------
__global__ __launch_bounds__(256) void qkv_kernel(
    const float* __restrict__ x,
    const float* __restrict__ wq,
    const float* __restrict__ wk,
    const float* __restrict__ wv)
{
    __shared__ float s_wq[128], s_wk[128], s_wv[128];

    const int t     = threadIdx.x;
    const int chunk = blockIdx.x >> 1;      // pixel chunk 0..15
    const int half  = blockIdx.x & 1;       // oc half 0..1
    const int g     = blockIdx.y;
    const int n     = blockIdx.z;

    if (t < 128) {
        const int wo = g * 256 + half * 128 + t;
        s_wq[t] = wq[wo];
        s_wk[t] = wk[wo];
        s_wv[t] = wv[wo];
    }
    __syncthreads();

    const int p = (chunk << 8) + t;                       // pixel within plane
    const size_t ibase = ((size_t)(n * 64 + g * 16) << 12) + p;

    const float* xb = x + ibase;
    float xv[16];
#pragma unroll
    for (int ic = 0; ic < 16; ic++) xv[ic] = xb[(size_t)ic << 12];

    const size_t obase = ibase + ((size_t)(half * 8) << 12);
    float* qb = g_q + obase;
    float* kb = g_k + obase;
    float* vb = g_v + obase;

#pragma unroll
    for (int oc = 0; oc < 8; oc++) {
        float q = 0.f, k = 0.f, v = 0.f;
#pragma unroll
        for (int ic = 0; ic < 16; ic++) {
            const float xi = xv[ic];
            q = fmaf(s_wq[oc * 16 + ic], xi, q);
            k = fmaf(s_wk[oc * 16 + ic], xi, k);
            v = fmaf(s_wv[oc * 16 + ic], xi, v);
        }
        qb[(size_t)oc << 12] = q;
        kb[(size_t)oc << 12] = k;
        vb[(size_t)oc << 12] = v;
    }
}

// ---------------------------------------------------------------------------
// Kernel 2: 7x7 local softmax attention per (n, c) plane.
//
// Math (exact rewrites of the reference):
//  * positional term q*r constant across taps -> cancels in softmax;
//    row_w/col_w dead.
//  * |q*k| small -> no max-subtraction needed in f32.
//  * exp(q*k) = ex2((q*log2e)*k), log2e folded once per pixel.
//  * zero-padded halo reproduces the reference padded taps exactly.
//
// R6: no local arrays in the hot loop. float4 lanes consumed directly via
// the constexpr selector; all accumulators are named scalars. Goal: remove
// the ~50% instruction bloat inferred from R4's issue accounting.
// ---------------------------------------------------------------------------
#define TILE_H   16
#define HALO_H   (TILE_H + 6)   // 22
#define HALO_W   72             // cols [-4, 68), multiple of 4 for LDS.128
#define HALO_SZ  (HALO_H * HALO_W)

__global__ __launch_bounds__(256, 4) void attn_kernel(float* __restrict__ out)
{
    __shared__ __align__(16) float sk[HALO_SZ];
    __shared__ __align__(16) float sv[HALO_SZ];

    const int c  = blockIdx.y;
    const int n  = blockIdx.z;
    const int y0 = blockIdx.x * TILE_H;

    const size_t plane = ((size_t)(n * 64 + c)) << 12;
    const float* __restrict__ kp = g_k + plane;
    const float* __restrict__ vp = g_v + plane;
    const float* __restrict__ qp = g_q + plane;

    // Thread t owns 4 consecutive pixels: p0 = 4t
    const int p0  = threadIdx.x << 2;
    const int ly  = p0 >> 6;          // 0..15
    const int lx0 = p0 & 63;          // multiple of 4

    // Issue the q load FIRST so its DRAM latency overlaps the halo loads.
    const float4 qv = *(const float4*)&qp[(y0 + ly) * 64 + lx0];

    // Cooperative zero-padded halo load: rows [y0-3, y0+19), cols [-4, 68)
    for (int idx = threadIdx.x; idx < HALO_SZ; idx += 256) {
        const int ry = idx / HALO_W;
        const int rx = idx - ry * HALO_W;
        const int gy = y0 - 3 + ry;
        const int gx = rx - 4;
        float kk = 0.f, vv = 0.f;
        if ((unsigned)gy < 64u && (unsigned)gx < 64u) {
            kk = kp[gy * 64 + gx];
            vv = vp[gy * 64 + gx];
        }
        sk[idx] = kk;
        sv[idx] = vv;
    }

    const float L2E = 1.4426950408889634f;
    const float q20 = qv.x * L2E;
    const float q21 = qv.y * L2E;
    const float q22 = qv.z * L2E;
    const float q23 = qv.w * L2E;

    float s0 = 0.f, s1 = 0.f, s2 = 0.f, s3 = 0.f;
    float a0 = 0.f, a1 = 0.f, a2 = 0.f, a3 = 0.f;

    __syncthreads();

    const int base = ly * HALO_W + lx0;   // smem word index of gx = lx0-4
#pragma unroll
    for (int dy = 0; dy < 7; dy++) {
        const float4* rk = (const float4*)&sk[base + dy * HALO_W];
        const float4* rv = (const float4*)&sv[base + dy * HALO_W];
        const float4 k0 = rk[0], k1 = rk[1], k2 = rk[2];
        const float4 v0 = rv[0], v1 = rv[1], v2 = rv[2];

        // Pixel j (0..3), tap dx (0..6) uses element (1 + j + dx).
        auto tap = [&](float q2, float& s, float& a, auto ic) {
            const float kx = elt<decltype(ic)::value>(k0, k1, k2);
            const float vx = elt<decltype(ic)::value>(v0, v1, v2);
            const float e = ex2f(q2 * kx);
            s += e;
            a = fmaf(e, vx, a);
        };

#pragma unroll
        for (int dx = 0; dx < 7; dx++) {
            switch (dx) {  // make (1+j+dx) a true compile-time constant
#define ROW(DX)                                                              \
            case DX:                                                         \
                tap(q20, s0, a0, std::integral_constant<int, 1 + 0 + DX>{}); \
                tap(q21, s1, a1, std::integral_constant<int, 1 + 1 + DX>{}); \
                tap(q22, s2, a2, std::integral_constant<int, 1 + 2 + DX>{}); \
                tap(q23, s3, a3, std::integral_constant<int, 1 + 3 + DX>{}); \
                break;
            ROW(0) ROW(1) ROW(2) ROW(3) ROW(4) ROW(5) ROW(6)
#undef ROW
            }
        }
    }

    float4 o;
    o.x = __fdividef(a0, s0);
    o.y = __fdividef(a1, s1);
    o.z = __fdividef(a2, s2);
    o.w = __fdividef(a3, s3);
    *(float4*)&out[plane + (y0 + ly) * 64 + lx0] = o;
}

// ---------------------------------------------------------------------------
// Launch. Inputs (metadata order): x, wq, wk, wv, row_w, col_w.
// row_w / col_w are mathematically dead (softmax cancellation) and ignored.
// ---------------------------------------------------------------------------
extern "C" void kernel_launch(void* const* d_in, const int* in_sizes, int n_in,
                              void* d_out, int out_size)
{
    const float* x  = (const float*)d_in[0];
    const float* wq = (const float*)d_in[1];
    const float* wk = (const float*)d_in[2];
    const float* wv = (const float*)d_in[3];
    float* out = (float*)d_out;

    (void)in_sizes; (void)n_in; (void)out_size;

    qkv_kernel<<<dim3(32, 4, 4), 256>>>(x, wq, wk, wv);
    attn_kernel<<<dim3(4, 64, 4), 256>>>(out);
}